// round 8
// baseline (speedup 1.0000x reference)
#include <cuda_runtime.h>
#include <cstdint>

#define BATCH 4
#define SEQ   4096
#define EMBED 1024
#define HEAD  64
#define ROWS  (BATCH * SEQ)
#define KSPLIT 3

#define LOG2E 1.4426950408889634f

__device__ float g_w [192 * EMBED];
__device__ float g_q [ROWS * HEAD];
__device__ float g_k [ROWS * HEAD];
__device__ float g_vt[BATCH * HEAD * SEQ];
__device__ float g_qn[ROWS];          // ||q_i|| (of rounded q)
__device__ int   g_kmax_i[BATCH];     // max_j ||k_j|| per batch, float-as-int
__device__ float g_opart[KSPLIT * ROWS * HEAD];
__device__ float g_l   [KSPLIT * ROWS];

// ---------------------------------------------------------------------------
__device__ __forceinline__ unsigned f2tf(float f) {
    unsigned u;
    asm("cvt.rna.tf32.f32 %0, %1;" : "=r"(u) : "f"(f));
    return u;
}
__device__ __forceinline__ float f2tff(float f) { return __uint_as_float(f2tf(f)); }

__device__ __forceinline__ void mma8(float* d, unsigned a0, unsigned a1,
                                     unsigned a2, unsigned a3,
                                     unsigned b0, unsigned b1) {
    asm("mma.sync.aligned.m16n8k8.row.col.f32.tf32.tf32.f32 "
        "{%0,%1,%2,%3},{%4,%5,%6,%7},{%8,%9},{%0,%1,%2,%3};"
        : "+f"(d[0]), "+f"(d[1]), "+f"(d[2]), "+f"(d[3])
        : "r"(a0), "r"(a1), "r"(a2), "r"(a3), "r"(b0), "r"(b1));
}

__device__ __forceinline__ void cp16(void* sptr, const void* gaddr) {
    uint32_t sa = (uint32_t)__cvta_generic_to_shared(sptr);
    asm volatile("cp.async.ca.shared.global [%0], [%1], 16;" ::"r"(sa), "l"(gaddr));
}
__device__ __forceinline__ void cp_commit() { asm volatile("cp.async.commit_group;"); }

// ===========================================================================
// Weight pre-round + kmax init
// ===========================================================================
__global__ void __launch_bounds__(256) wcvt_kernel(const float* __restrict__ Wq,
                                                   const float* __restrict__ Wk,
                                                   const float* __restrict__ Wv) {
    if (blockIdx.x == 0 && threadIdx.x < BATCH) g_kmax_i[threadIdx.x] = 0;
    int idx4 = blockIdx.x * 256 + threadIdx.x;
    int n  = idx4 >> 8;
    int e4 = idx4 & 255;
    const float* src = (n < 64) ? Wq : (n < 128) ? Wk : Wv;
    float4 v = *(const float4*)(src + (size_t)(n & 63) * EMBED + 4 * e4);
    v.x = f2tff(v.x); v.y = f2tff(v.y); v.z = f2tff(v.z); v.w = f2tff(v.w);
    *(float4*)(g_w + (size_t)n * EMBED + 4 * e4) = v;
}

// ===========================================================================
// Projection (tf32 mma): tile 64 rows x 192 cols, 256 threads.
// ===========================================================================
#define PKC   32
#define PSTR  40
#define XS_F  (64 * PSTR)
#define WS_F  (192 * PSTR)
#define PROJ_SMEM_F (2 * (XS_F + WS_F))
#define PROJ_SMEM_B (PROJ_SMEM_F * 4)

__global__ void __launch_bounds__(256, 2)
proj_kernel(const float* __restrict__ x) {
    extern __shared__ float sm[];
    const int t = threadIdx.x, lane = t & 31, wid = t >> 5;
    const int g = lane >> 2, tq = lane & 3;
    const int wm = wid & 1, wn = wid >> 1;
    const size_t row0 = (size_t)blockIdx.x * 64;

    float acc[2][6][4];
#pragma unroll
    for (int mt = 0; mt < 2; mt++)
#pragma unroll
        for (int nt = 0; nt < 6; nt++)
#pragma unroll
            for (int i = 0; i < 4; i++) acc[mt][nt][i] = 0.f;

    const int NC = EMBED / PKC;

    auto issue = [&](int c) {
        int buf = c & 1;
        int k0  = c * PKC;
        float* Xs = sm + buf * (XS_F + WS_F);
        float* Ws = Xs + XS_F;
#pragma unroll
        for (int j = 0; j < 2; j++) {
            int id = t + 256 * j;
            int r = id >> 3, q = id & 7;
            cp16(&Xs[r * PSTR + 4 * q], x + (row0 + r) * EMBED + k0 + 4 * q);
        }
#pragma unroll
        for (int j = 0; j < 6; j++) {
            int id = t + 256 * j;
            int n = id >> 3, q = id & 7;
            cp16(&Ws[n * PSTR + 4 * q], g_w + (size_t)n * EMBED + k0 + 4 * q);
        }
        cp_commit();
    };

    issue(0);
    for (int c = 0; c < NC; c++) {
        if (c + 1 < NC) {
            issue(c + 1);
            asm volatile("cp.async.wait_group 1;");
        } else {
            asm volatile("cp.async.wait_group 0;");
        }
        __syncthreads();
        const float* Xs = sm + (c & 1) * (XS_F + WS_F);
        const float* Ws = Xs + XS_F;
#pragma unroll
        for (int kk = 0; kk < 4; kk++) {
            unsigned a[2][4];
#pragma unroll
            for (int mt = 0; mt < 2; mt++) {
                int r = 32 * wm + 16 * mt + g;
                float2 lo = *(const float2*)&Xs[(r    ) * PSTR + 8 * kk + 2 * tq];
                float2 hi = *(const float2*)&Xs[(r + 8) * PSTR + 8 * kk + 2 * tq];
                a[mt][0] = f2tf(lo.x); a[mt][1] = f2tf(hi.x);
                a[mt][2] = f2tf(lo.y); a[mt][3] = f2tf(hi.y);
            }
#pragma unroll
            for (int nt = 0; nt < 6; nt++) {
                uint2 bb = *(const uint2*)&Ws[(48 * wn + 8 * nt + g) * PSTR + 8 * kk + 2 * tq];
#pragma unroll
                for (int mt = 0; mt < 2; mt++)
                    mma8(acc[mt][nt], a[mt][0], a[mt][1], a[mt][2], a[mt][3],
                         bb.x, bb.y);
            }
        }
        __syncthreads();
    }

#pragma unroll
    for (int mt = 0; mt < 2; mt++) {
#pragma unroll
        for (int nt = 0; nt < 6; nt++) {
            int c0 = 48 * wn + 8 * nt + 2 * tq;
            int msel = c0 >> 6;
            int h    = c0 & 63;
            int r1 = (int)row0 + 32 * wm + 16 * mt + g;
            int r2 = r1 + 8;
            float* a = acc[mt][nt];
            float a0 = f2tff(a[0]), a1 = f2tff(a[1]);
            float a2 = f2tff(a[2]), a3 = f2tff(a[3]);
            if (msel == 0) {
                *(float2*)&g_q[(size_t)r1 * 64 + h] = make_float2(a0, a1);
                *(float2*)&g_q[(size_t)r2 * 64 + h] = make_float2(a2, a3);
            } else if (msel == 1) {
                *(float2*)&g_k[(size_t)r1 * 64 + h] = make_float2(a0, a1);
                *(float2*)&g_k[(size_t)r2 * 64 + h] = make_float2(a2, a3);
            } else {
                int b1 = r1 >> 12, n1 = r1 & 4095;
                int b2 = r2 >> 12, n2 = r2 & 4095;
                g_vt[((size_t)b1 * 64 + h    ) * SEQ + n1] = a0;
                g_vt[((size_t)b1 * 64 + h + 1) * SEQ + n1] = a1;
                g_vt[((size_t)b2 * 64 + h    ) * SEQ + n2] = a2;
                g_vt[((size_t)b2 * 64 + h + 1) * SEQ + n2] = a3;
            }
        }
    }
}

// ===========================================================================
// Norms
// ===========================================================================
__global__ void __launch_bounds__(128) norm_kernel() {
    int row = blockIdx.x * 128 + threadIdx.x;
    float nq = 0.f, nk = 0.f;
#pragma unroll
    for (int i = 0; i < 16; i++) {
        float4 qv = *(const float4*)&g_q[(size_t)row * 64 + 4 * i];
        float4 kv = *(const float4*)&g_k[(size_t)row * 64 + 4 * i];
        nq += qv.x * qv.x + qv.y * qv.y + qv.z * qv.z + qv.w * qv.w;
        nk += kv.x * kv.x + kv.y * kv.y + kv.z * kv.z + kv.w * kv.w;
    }
    g_qn[row] = sqrtf(nq);
    float nkr = sqrtf(nk);
#pragma unroll
    for (int d = 16; d; d >>= 1)
        nkr = fmaxf(nkr, __shfl_xor_sync(0xffffffffu, nkr, d));
    if ((threadIdx.x & 31) == 0)
        atomicMax(&g_kmax_i[row >> 12], __float_as_int(nkr));
}

// ===========================================================================
// Flash attention, tf32 mma, static max, fused S->exp->PV.
// Smem: TWO 64x72 K/V regions; region A doubles as the Q staging buffer
// (Q hoisted to registers, then A is recycled for odd tiles).
// 128 threads (4 warps x 32 rows), 3 CTAs/SM, grid 384 (split-K x3, 22/21/21).
// ===========================================================================
#define STR 72
#define REG_F (2 * 64 * STR)          // 9216 floats per region (K 64x72 + V 64x72)
#define S_A   0                       // region A (Q staging, then odd tiles)
#define S_B   REG_F                   // region B (even tiles)
#define S_M   (2 * REG_F)             // mask [2][64]
#define ATTN_SMEM_F (S_M + 128)       // 18560
#define ATTN_SMEM_B (ATTN_SMEM_F * 4) // 74240 B

__global__ void __launch_bounds__(128, 3)
attn_kernel(const int* __restrict__ mask) {
    extern __shared__ float sm[];
    float* Mb = sm + S_M;

    const int t = threadIdx.x, lane = t & 31;
    const int g = lane >> 2, tq = lane & 3;
    const int r0 = (t >> 5) * 32;
    const int b  = blockIdx.y, z = blockIdx.z;
    const int q0 = blockIdx.x * 128;

    const int startTile = (z == 0) ? 0 : 22 + 21 * (z - 1);
    const int ntz       = (z == 0) ? 22 : 21;
    const int koff      = startTile * 64;

    const float* qbase = g_q + ((size_t)b * SEQ + q0) * HEAD;
    const float* kbase = g_k + ((size_t)b * SEQ + koff) * HEAD;
    const float* vbase = g_vt + (size_t)b * HEAD * SEQ + koff;

    // region for tile it: odd -> A (recycled Q buffer), even -> B
    auto region = [&](int it) -> float* { return sm + ((it & 1) ? S_A : S_B); };

    // ---- stage Q into region A (128 rows x 64 -> laid out as 128 x 72) ----
    {
        float* Qs = sm + S_A;
#pragma unroll
        for (int j = 0; j < 16; j++) {
            int id = t + 128 * j;
            int r = id >> 4, q = id & 15;
            cp16(&Qs[r * STR + 4 * q], qbase + (size_t)r * 64 + 4 * q);
        }
        cp_commit();
    }

    auto issue = [&](int it) {
        float* Ks = region(it);
        float* Vs = Ks + 64 * STR;
#pragma unroll
        for (int j = 0; j < 8; j++) {
            int id = t + 128 * j;
            int r = id >> 4, q = id & 15;
            cp16(&Ks[r * STR + 4 * q], kbase + (size_t)(it * 64 + r) * 64 + 4 * q);
            cp16(&Vs[r * STR + 4 * q], vbase + (size_t)r * SEQ + it * 64 + 4 * q);
        }
        if (t < 64)
            Mb[(it & 1) * 64 + t] =
                (mask[b * SEQ + koff + it * 64 + t] == 0) ? 0.f : 1.f;
        cp_commit();
    };

    issue(0);                               // tile 0 -> region B

    // ---- static row bounds (log2 domain) ----
    const float SC2 = 0.125f * LOG2E;
    const float kmax = __int_as_float(g_kmax_i[b]);
    float negM[2][2];
#pragma unroll
    for (int rg = 0; rg < 2; rg++) {
        size_t rr = (size_t)b * SEQ + q0 + r0 + 16 * rg + g;
        negM[rg][0] = -g_qn[rr]     * kmax * SC2;
        negM[rg][1] = -g_qn[rr + 8] * kmax * SC2;
    }

    asm volatile("cp.async.wait_group 1;"); // Q group drained
    __syncthreads();

    // ---- hoist Q fragments from region A ----
    unsigned qa[2][8][4];
    {
        const float* Qs = sm + S_A;
#pragma unroll
        for (int rg = 0; rg < 2; rg++)
#pragma unroll
            for (int kk = 0; kk < 8; kk++) {
                uint2 lo = *(const uint2*)&Qs[(r0 + 16 * rg + g    ) * STR + 8 * kk + 2 * tq];
                uint2 hi = *(const uint2*)&Qs[(r0 + 16 * rg + g + 8) * STR + 8 * kk + 2 * tq];
                qa[rg][kk][0] = lo.x; qa[rg][kk][1] = hi.x;
                qa[rg][kk][2] = lo.y; qa[rg][kk][3] = hi.y;
            }
    }
    __syncthreads();                        // everyone done reading A
    if (1 < ntz) issue(1);                  // tile 1 -> region A

    float l[2][2] = {{0.f, 0.f}, {0.f, 0.f}};
    float o[2][8][4];
#pragma unroll
    for (int rg = 0; rg < 2; rg++)
#pragma unroll
        for (int nt = 0; nt < 8; nt++)
#pragma unroll
            for (int i = 0; i < 4; i++) o[rg][nt][i] = 0.f;

    for (int it = 0; it < ntz; it++) {
        if (it >= 1 && it + 1 < ntz) issue(it + 1);
        if (it + 1 < ntz) {
            asm volatile("cp.async.wait_group 1;");
        } else {
            asm volatile("cp.async.wait_group 0;");
        }
        __syncthreads();
        const float* Ks = region(it);
        const float* Vs = Ks + 64 * STR;
        const float* mk = Mb + (it & 1) * 64;

#pragma unroll
        for (int nt = 0; nt < 8; nt++) {
            float s0[4] = {0.f, 0.f, 0.f, 0.f};
            float s1[4] = {0.f, 0.f, 0.f, 0.f};
#pragma unroll
            for (int kk = 0; kk < 8; kk++) {
                uint2 bb = *(const uint2*)&Ks[(8 * nt + g) * STR + 8 * kk + 2 * tq];
                mma8(s0, qa[0][kk][0], qa[0][kk][1], qa[0][kk][2], qa[0][kk][3],
                     bb.x, bb.y);
                mma8(s1, qa[1][kk][0], qa[1][kk][1], qa[1][kk][2], qa[1][kk][3],
                     bb.x, bb.y);
            }
            float2 mm = *(const float2*)&mk[8 * nt + 2 * tq];
            float p00 = exp2f(fmaf(s0[0], SC2, negM[0][0])) * mm.x;
            float p01 = exp2f(fmaf(s0[1], SC2, negM[0][0])) * mm.y;
            float p02 = exp2f(fmaf(s0[2], SC2, negM[0][1])) * mm.x;
            float p03 = exp2f(fmaf(s0[3], SC2, negM[0][1])) * mm.y;
            float p10 = exp2f(fmaf(s1[0], SC2, negM[1][0])) * mm.x;
            float p11 = exp2f(fmaf(s1[1], SC2, negM[1][0])) * mm.y;
            float p12 = exp2f(fmaf(s1[2], SC2, negM[1][1])) * mm.x;
            float p13 = exp2f(fmaf(s1[3], SC2, negM[1][1])) * mm.y;
            unsigned u00 = f2tf(p00), u01 = f2tf(p01), u02 = f2tf(p02), u03 = f2tf(p03);
            unsigned u10 = f2tf(p10), u11 = f2tf(p11), u12 = f2tf(p12), u13 = f2tf(p13);
            l[0][0] += __uint_as_float(u00) + __uint_as_float(u01);
            l[0][1] += __uint_as_float(u02) + __uint_as_float(u03);
            l[1][0] += __uint_as_float(u10) + __uint_as_float(u11);
            l[1][1] += __uint_as_float(u12) + __uint_as_float(u13);
#pragma unroll
            for (int nh = 0; nh < 8; nh++) {
                uint2 bb = *(const uint2*)&Vs[(8 * nh + g) * STR + 8 * nt + 2 * tq];
                mma8(o[0][nh], u00, u02, u01, u03, bb.x, bb.y);
                mma8(o[1][nh], u10, u12, u11, u13, bb.x, bb.y);
            }
        }
        __syncthreads();
    }

    // ---- epilogue: reduce l across tq, store unnormalized O + l ----
#pragma unroll
    for (int rg = 0; rg < 2; rg++)
#pragma unroll
        for (int h = 0; h < 2; h++) {
            l[rg][h] += __shfl_xor_sync(0xffffffffu, l[rg][h], 1);
            l[rg][h] += __shfl_xor_sync(0xffffffffu, l[rg][h], 2);
        }
#pragma unroll
    for (int rg = 0; rg < 2; rg++) {
        size_t rlo = (size_t)z * ROWS + (size_t)b * SEQ + q0 + r0 + 16 * rg + g;
        size_t rhi = rlo + 8;
#pragma unroll
        for (int nt = 0; nt < 8; nt++) {
            int c0 = 8 * nt + 2 * tq;
            *(float2*)&g_opart[rlo * 64 + c0] = make_float2(o[rg][nt][0], o[rg][nt][1]);
            *(float2*)&g_opart[rhi * 64 + c0] = make_float2(o[rg][nt][2], o[rg][nt][3]);
        }
        if (tq == 0) {
            g_l[rlo] = l[rg][0];
            g_l[rhi] = l[rg][1];
        }
    }
}

// ===========================================================================
// Split-K combine: shift M is identical across splits -> plain sums.
// ===========================================================================
__global__ void __launch_bounds__(256) combine_kernel(float* __restrict__ out) {
    int t = threadIdx.x;
    int row = blockIdx.x * 16 + (t >> 4);
    int c   = (t & 15) * 4;
    float lsum = g_l[row] + g_l[ROWS + row] + g_l[2 * ROWS + row];
    float inv = 1.f / lsum;
    float4 a = *(const float4*)&g_opart[(size_t)row * 64 + c];
    float4 d = *(const float4*)&g_opart[((size_t)ROWS + row) * 64 + c];
    float4 e = *(const float4*)&g_opart[((size_t)2 * ROWS + row) * 64 + c];
    float4 r = make_float4((a.x + d.x + e.x) * inv, (a.y + d.y + e.y) * inv,
                           (a.z + d.z + e.z) * inv, (a.w + d.w + e.w) * inv);
    *(float4*)&out[(size_t)row * 64 + c] = r;
}

// ---------------------------------------------------------------------------
extern "C" void kernel_launch(void* const* d_in, const int* in_sizes, int n_in,
                              void* d_out, int out_size) {
    const float* x    = (const float*)d_in[0];
    const float* Wq   = (const float*)d_in[1];
    const float* Wk   = (const float*)d_in[2];
    const float* Wv   = (const float*)d_in[3];
    const int*   mask = (const int*)d_in[4];
    float*       out  = (float*)d_out;

    cudaFuncSetAttribute(proj_kernel, cudaFuncAttributeMaxDynamicSharedMemorySize,
                         PROJ_SMEM_B);
    cudaFuncSetAttribute(attn_kernel, cudaFuncAttributeMaxDynamicSharedMemorySize,
                         ATTN_SMEM_B);

    wcvt_kernel<<<192, 256>>>(Wq, Wk, Wv);
    proj_kernel<<<ROWS / 64, 256, PROJ_SMEM_B>>>(x);
    norm_kernel<<<ROWS / 128, 128>>>();
    attn_kernel<<<dim3(SEQ / 128, BATCH, KSPLIT), 128, ATTN_SMEM_B>>>(mask);
    combine_kernel<<<ROWS / 16, 256>>>(out);
}

// round 9
// speedup vs baseline: 1.0105x; 1.0105x over previous
#include <cuda_runtime.h>
#include <cstdint>

#define BATCH 4
#define SEQ   4096
#define EMBED 1024
#define HEAD  64
#define ROWS  (BATCH * SEQ)
#define KSPLIT 3

#define LOG2E 1.4426950408889634f

__device__ float g_w [192 * EMBED];
__device__ float g_q [ROWS * HEAD];
__device__ float g_k [ROWS * HEAD];
__device__ float g_vt[BATCH * HEAD * SEQ];
__device__ float g_qn[ROWS];          // ||q_i|| (of rounded q)
__device__ int   g_kmax_i[BATCH];     // max_j ||k_j|| per batch, float-as-int
__device__ float g_opart[KSPLIT * ROWS * HEAD];
__device__ float g_l   [KSPLIT * ROWS];

// ---------------------------------------------------------------------------
__device__ __forceinline__ unsigned f2tf(float f) {
    unsigned u;
    asm("cvt.rna.tf32.f32 %0, %1;" : "=r"(u) : "f"(f));
    return u;
}
__device__ __forceinline__ float f2tff(float f) { return __uint_as_float(f2tf(f)); }

__device__ __forceinline__ void mma8(float* d, unsigned a0, unsigned a1,
                                     unsigned a2, unsigned a3,
                                     unsigned b0, unsigned b1) {
    asm("mma.sync.aligned.m16n8k8.row.col.f32.tf32.tf32.f32 "
        "{%0,%1,%2,%3},{%4,%5,%6,%7},{%8,%9},{%0,%1,%2,%3};"
        : "+f"(d[0]), "+f"(d[1]), "+f"(d[2]), "+f"(d[3])
        : "r"(a0), "r"(a1), "r"(a2), "r"(a3), "r"(b0), "r"(b1));
}

__device__ __forceinline__ void cp16(void* sptr, const void* gaddr) {
    uint32_t sa = (uint32_t)__cvta_generic_to_shared(sptr);
    asm volatile("cp.async.ca.shared.global [%0], [%1], 16;" ::"r"(sa), "l"(gaddr));
}
__device__ __forceinline__ void cp_commit() { asm volatile("cp.async.commit_group;"); }

// ===========================================================================
// Weight pre-round + kmax init
// ===========================================================================
__global__ void __launch_bounds__(256) wcvt_kernel(const float* __restrict__ Wq,
                                                   const float* __restrict__ Wk,
                                                   const float* __restrict__ Wv) {
    if (blockIdx.x == 0 && threadIdx.x < BATCH) g_kmax_i[threadIdx.x] = 0;
    int idx4 = blockIdx.x * 256 + threadIdx.x;
    int n  = idx4 >> 8;
    int e4 = idx4 & 255;
    const float* src = (n < 64) ? Wq : (n < 128) ? Wk : Wv;
    float4 v = *(const float4*)(src + (size_t)(n & 63) * EMBED + 4 * e4);
    v.x = f2tff(v.x); v.y = f2tff(v.y); v.z = f2tff(v.z); v.w = f2tff(v.w);
    *(float4*)(g_w + (size_t)n * EMBED + 4 * e4) = v;
}

// ===========================================================================
// Projection (tf32 mma): tile 64 rows x 192 cols, 256 threads.
// ===========================================================================
#define PKC   32
#define PSTR  40
#define XS_F  (64 * PSTR)
#define WS_F  (192 * PSTR)
#define PROJ_SMEM_F (2 * (XS_F + WS_F))
#define PROJ_SMEM_B (PROJ_SMEM_F * 4)

__global__ void __launch_bounds__(256, 2)
proj_kernel(const float* __restrict__ x) {
    extern __shared__ float sm[];
    const int t = threadIdx.x, lane = t & 31, wid = t >> 5;
    const int g = lane >> 2, tq = lane & 3;
    const int wm = wid & 1, wn = wid >> 1;
    const size_t row0 = (size_t)blockIdx.x * 64;

    float acc[2][6][4];
#pragma unroll
    for (int mt = 0; mt < 2; mt++)
#pragma unroll
        for (int nt = 0; nt < 6; nt++)
#pragma unroll
            for (int i = 0; i < 4; i++) acc[mt][nt][i] = 0.f;

    const int NC = EMBED / PKC;

    auto issue = [&](int c) {
        int buf = c & 1;
        int k0  = c * PKC;
        float* Xs = sm + buf * (XS_F + WS_F);
        float* Ws = Xs + XS_F;
#pragma unroll
        for (int j = 0; j < 2; j++) {
            int id = t + 256 * j;
            int r = id >> 3, q = id & 7;
            cp16(&Xs[r * PSTR + 4 * q], x + (row0 + r) * EMBED + k0 + 4 * q);
        }
#pragma unroll
        for (int j = 0; j < 6; j++) {
            int id = t + 256 * j;
            int n = id >> 3, q = id & 7;
            cp16(&Ws[n * PSTR + 4 * q], g_w + (size_t)n * EMBED + k0 + 4 * q);
        }
        cp_commit();
    };

    issue(0);
    for (int c = 0; c < NC; c++) {
        if (c + 1 < NC) {
            issue(c + 1);
            asm volatile("cp.async.wait_group 1;");
        } else {
            asm volatile("cp.async.wait_group 0;");
        }
        __syncthreads();
        const float* Xs = sm + (c & 1) * (XS_F + WS_F);
        const float* Ws = Xs + XS_F;
#pragma unroll
        for (int kk = 0; kk < 4; kk++) {
            unsigned a[2][4];
#pragma unroll
            for (int mt = 0; mt < 2; mt++) {
                int r = 32 * wm + 16 * mt + g;
                float2 lo = *(const float2*)&Xs[(r    ) * PSTR + 8 * kk + 2 * tq];
                float2 hi = *(const float2*)&Xs[(r + 8) * PSTR + 8 * kk + 2 * tq];
                a[mt][0] = f2tf(lo.x); a[mt][1] = f2tf(hi.x);
                a[mt][2] = f2tf(lo.y); a[mt][3] = f2tf(hi.y);
            }
#pragma unroll
            for (int nt = 0; nt < 6; nt++) {
                uint2 bb = *(const uint2*)&Ws[(48 * wn + 8 * nt + g) * PSTR + 8 * kk + 2 * tq];
#pragma unroll
                for (int mt = 0; mt < 2; mt++)
                    mma8(acc[mt][nt], a[mt][0], a[mt][1], a[mt][2], a[mt][3],
                         bb.x, bb.y);
            }
        }
        __syncthreads();
    }

#pragma unroll
    for (int mt = 0; mt < 2; mt++) {
#pragma unroll
        for (int nt = 0; nt < 6; nt++) {
            int c0 = 48 * wn + 8 * nt + 2 * tq;
            int msel = c0 >> 6;
            int h    = c0 & 63;
            int r1 = (int)row0 + 32 * wm + 16 * mt + g;
            int r2 = r1 + 8;
            float* a = acc[mt][nt];
            float a0 = f2tff(a[0]), a1 = f2tff(a[1]);
            float a2 = f2tff(a[2]), a3 = f2tff(a[3]);
            if (msel == 0) {
                *(float2*)&g_q[(size_t)r1 * 64 + h] = make_float2(a0, a1);
                *(float2*)&g_q[(size_t)r2 * 64 + h] = make_float2(a2, a3);
            } else if (msel == 1) {
                *(float2*)&g_k[(size_t)r1 * 64 + h] = make_float2(a0, a1);
                *(float2*)&g_k[(size_t)r2 * 64 + h] = make_float2(a2, a3);
            } else {
                int b1 = r1 >> 12, n1 = r1 & 4095;
                int b2 = r2 >> 12, n2 = r2 & 4095;
                g_vt[((size_t)b1 * 64 + h    ) * SEQ + n1] = a0;
                g_vt[((size_t)b1 * 64 + h + 1) * SEQ + n1] = a1;
                g_vt[((size_t)b2 * 64 + h    ) * SEQ + n2] = a2;
                g_vt[((size_t)b2 * 64 + h + 1) * SEQ + n2] = a3;
            }
        }
    }
}

// ===========================================================================
// Norms
// ===========================================================================
__global__ void __launch_bounds__(128) norm_kernel() {
    int row = blockIdx.x * 128 + threadIdx.x;
    float nq = 0.f, nk = 0.f;
#pragma unroll
    for (int i = 0; i < 16; i++) {
        float4 qv = *(const float4*)&g_q[(size_t)row * 64 + 4 * i];
        float4 kv = *(const float4*)&g_k[(size_t)row * 64 + 4 * i];
        nq += qv.x * qv.x + qv.y * qv.y + qv.z * qv.z + qv.w * qv.w;
        nk += kv.x * kv.x + kv.y * kv.y + kv.z * kv.z + kv.w * kv.w;
    }
    g_qn[row] = sqrtf(nq);
    float nkr = sqrtf(nk);
#pragma unroll
    for (int d = 16; d; d >>= 1)
        nkr = fmaxf(nkr, __shfl_xor_sync(0xffffffffu, nkr, d));
    if ((threadIdx.x & 31) == 0)
        atomicMax(&g_kmax_i[row >> 12], __float_as_int(nkr));
}

// ===========================================================================
// Flash attention, tf32 mma, static max, fused S->exp->PV.
// S-phase K-reduction split into two half-accumulators -> 4 independent
// mma chains per warp (depth 4) to cover HMMA accumulator-reuse latency.
// Smem: two 64x72 K/V regions; region A doubles as Q staging.
// 128 threads (4 warps x 32 rows), 3 CTAs/SM, grid 384 (split-K x3).
// ===========================================================================
#define STR 72
#define REG_F (2 * 64 * STR)
#define S_A   0
#define S_B   REG_F
#define S_M   (2 * REG_F)
#define ATTN_SMEM_F (S_M + 128)
#define ATTN_SMEM_B (ATTN_SMEM_F * 4) // 74240 B

__global__ void __launch_bounds__(128, 3)
attn_kernel(const int* __restrict__ mask) {
    extern __shared__ float sm[];
    float* Mb = sm + S_M;

    const int t = threadIdx.x, lane = t & 31;
    const int g = lane >> 2, tq = lane & 3;
    const int r0 = (t >> 5) * 32;
    const int b  = blockIdx.y, z = blockIdx.z;
    const int q0 = blockIdx.x * 128;

    const int startTile = (z == 0) ? 0 : 22 + 21 * (z - 1);
    const int ntz       = (z == 0) ? 22 : 21;
    const int koff      = startTile * 64;

    const float* qbase = g_q + ((size_t)b * SEQ + q0) * HEAD;
    const float* kbase = g_k + ((size_t)b * SEQ + koff) * HEAD;
    const float* vbase = g_vt + (size_t)b * HEAD * SEQ + koff;

    auto region = [&](int it) -> float* { return sm + ((it & 1) ? S_A : S_B); };

    // ---- stage Q into region A ----
    {
        float* Qs = sm + S_A;
#pragma unroll
        for (int j = 0; j < 16; j++) {
            int id = t + 128 * j;
            int r = id >> 4, q = id & 15;
            cp16(&Qs[r * STR + 4 * q], qbase + (size_t)r * 64 + 4 * q);
        }
        cp_commit();
    }

    auto issue = [&](int it) {
        float* Ks = region(it);
        float* Vs = Ks + 64 * STR;
#pragma unroll
        for (int j = 0; j < 8; j++) {
            int id = t + 128 * j;
            int r = id >> 4, q = id & 15;
            cp16(&Ks[r * STR + 4 * q], kbase + (size_t)(it * 64 + r) * 64 + 4 * q);
            cp16(&Vs[r * STR + 4 * q], vbase + (size_t)r * SEQ + it * 64 + 4 * q);
        }
        if (t < 64)
            Mb[(it & 1) * 64 + t] =
                (mask[b * SEQ + koff + it * 64 + t] == 0) ? 0.f : 1.f;
        cp_commit();
    };

    issue(0);                               // tile 0 -> region B

    // ---- static row bounds (log2 domain) ----
    const float SC2 = 0.125f * LOG2E;
    const float kmax = __int_as_float(g_kmax_i[b]);
    float negM[2][2];
#pragma unroll
    for (int rg = 0; rg < 2; rg++) {
        size_t rr = (size_t)b * SEQ + q0 + r0 + 16 * rg + g;
        negM[rg][0] = -g_qn[rr]     * kmax * SC2;
        negM[rg][1] = -g_qn[rr + 8] * kmax * SC2;
    }

    asm volatile("cp.async.wait_group 1;"); // Q group drained
    __syncthreads();

    // ---- hoist Q fragments from region A ----
    unsigned qa[2][8][4];
    {
        const float* Qs = sm + S_A;
#pragma unroll
        for (int rg = 0; rg < 2; rg++)
#pragma unroll
            for (int kk = 0; kk < 8; kk++) {
                uint2 lo = *(const uint2*)&Qs[(r0 + 16 * rg + g    ) * STR + 8 * kk + 2 * tq];
                uint2 hi = *(const uint2*)&Qs[(r0 + 16 * rg + g + 8) * STR + 8 * kk + 2 * tq];
                qa[rg][kk][0] = lo.x; qa[rg][kk][1] = hi.x;
                qa[rg][kk][2] = lo.y; qa[rg][kk][3] = hi.y;
            }
    }
    __syncthreads();                        // everyone done reading A
    if (1 < ntz) issue(1);                  // tile 1 -> region A

    float l[2][2] = {{0.f, 0.f}, {0.f, 0.f}};
    float o[2][8][4];
#pragma unroll
    for (int rg = 0; rg < 2; rg++)
#pragma unroll
        for (int nt = 0; nt < 8; nt++)
#pragma unroll
            for (int i = 0; i < 4; i++) o[rg][nt][i] = 0.f;

    for (int it = 0; it < ntz; it++) {
        if (it >= 1 && it + 1 < ntz) issue(it + 1);
        if (it + 1 < ntz) {
            asm volatile("cp.async.wait_group 1;");
        } else {
            asm volatile("cp.async.wait_group 0;");
        }
        __syncthreads();
        const float* Ks = region(it);
        const float* Vs = Ks + 64 * STR;
        const float* mk = Mb + (it & 1) * 64;

#pragma unroll
        for (int nt = 0; nt < 8; nt++) {
            // ---- S chunk: 4 independent accumulator chains, depth 4 ----
            float s0a[4] = {0.f, 0.f, 0.f, 0.f};
            float s1a[4] = {0.f, 0.f, 0.f, 0.f};
            float s0b[4] = {0.f, 0.f, 0.f, 0.f};
            float s1b[4] = {0.f, 0.f, 0.f, 0.f};
#pragma unroll
            for (int kk = 0; kk < 4; kk++) {
                uint2 ba = *(const uint2*)&Ks[(8 * nt + g) * STR + 8 * kk + 2 * tq];
                uint2 bc = *(const uint2*)&Ks[(8 * nt + g) * STR + 8 * (kk + 4) + 2 * tq];
                mma8(s0a, qa[0][kk][0], qa[0][kk][1], qa[0][kk][2], qa[0][kk][3],
                     ba.x, ba.y);
                mma8(s1a, qa[1][kk][0], qa[1][kk][1], qa[1][kk][2], qa[1][kk][3],
                     ba.x, ba.y);
                mma8(s0b, qa[0][kk + 4][0], qa[0][kk + 4][1], qa[0][kk + 4][2],
                     qa[0][kk + 4][3], bc.x, bc.y);
                mma8(s1b, qa[1][kk + 4][0], qa[1][kk + 4][1], qa[1][kk + 4][2],
                     qa[1][kk + 4][3], bc.x, bc.y);
            }
            float s0[4], s1[4];
#pragma unroll
            for (int i = 0; i < 4; i++) {
                s0[i] = s0a[i] + s0b[i];
                s1[i] = s1a[i] + s1b[i];
            }
            // ---- static-max softmax, elementwise ----
            float2 mm = *(const float2*)&mk[8 * nt + 2 * tq];
            float p00 = exp2f(fmaf(s0[0], SC2, negM[0][0])) * mm.x;
            float p01 = exp2f(fmaf(s0[1], SC2, negM[0][0])) * mm.y;
            float p02 = exp2f(fmaf(s0[2], SC2, negM[0][1])) * mm.x;
            float p03 = exp2f(fmaf(s0[3], SC2, negM[0][1])) * mm.y;
            float p10 = exp2f(fmaf(s1[0], SC2, negM[1][0])) * mm.x;
            float p11 = exp2f(fmaf(s1[1], SC2, negM[1][0])) * mm.y;
            float p12 = exp2f(fmaf(s1[2], SC2, negM[1][1])) * mm.x;
            float p13 = exp2f(fmaf(s1[3], SC2, negM[1][1])) * mm.y;
            unsigned u00 = f2tf(p00), u01 = f2tf(p01), u02 = f2tf(p02), u03 = f2tf(p03);
            unsigned u10 = f2tf(p10), u11 = f2tf(p11), u12 = f2tf(p12), u13 = f2tf(p13);
            l[0][0] += __uint_as_float(u00) + __uint_as_float(u01);
            l[0][1] += __uint_as_float(u02) + __uint_as_float(u03);
            l[1][0] += __uint_as_float(u10) + __uint_as_float(u11);
            l[1][1] += __uint_as_float(u12) + __uint_as_float(u13);
            // ---- PV chunk ----
#pragma unroll
            for (int nh = 0; nh < 8; nh++) {
                uint2 bb = *(const uint2*)&Vs[(8 * nh + g) * STR + 8 * nt + 2 * tq];
                mma8(o[0][nh], u00, u02, u01, u03, bb.x, bb.y);
                mma8(o[1][nh], u10, u12, u11, u13, bb.x, bb.y);
            }
        }
        __syncthreads();
    }

    // ---- epilogue: reduce l across tq, store unnormalized O + l ----
#pragma unroll
    for (int rg = 0; rg < 2; rg++)
#pragma unroll
        for (int h = 0; h < 2; h++) {
            l[rg][h] += __shfl_xor_sync(0xffffffffu, l[rg][h], 1);
            l[rg][h] += __shfl_xor_sync(0xffffffffu, l[rg][h], 2);
        }
#pragma unroll
    for (int rg = 0; rg < 2; rg++) {
        size_t rlo = (size_t)z * ROWS + (size_t)b * SEQ + q0 + r0 + 16 * rg + g;
        size_t rhi = rlo + 8;
#pragma unroll
        for (int nt = 0; nt < 8; nt++) {
            int c0 = 8 * nt + 2 * tq;
            *(float2*)&g_opart[rlo * 64 + c0] = make_float2(o[rg][nt][0], o[rg][nt][1]);
            *(float2*)&g_opart[rhi * 64 + c0] = make_float2(o[rg][nt][2], o[rg][nt][3]);
        }
        if (tq == 0) {
            g_l[rlo] = l[rg][0];
            g_l[rhi] = l[rg][1];
        }
    }
}

// ===========================================================================
// Split-K combine: shift M identical across splits -> plain sums.
// ===========================================================================
__global__ void __launch_bounds__(256) combine_kernel(float* __restrict__ out) {
    int t = threadIdx.x;
    int row = blockIdx.x * 16 + (t >> 4);
    int c   = (t & 15) * 4;
    float lsum = g_l[row] + g_l[ROWS + row] + g_l[2 * ROWS + row];
    float inv = 1.f / lsum;
    float4 a = *(const float4*)&g_opart[(size_t)row * 64 + c];
    float4 d = *(const float4*)&g_opart[((size_t)ROWS + row) * 64 + c];
    float4 e = *(const float4*)&g_opart[((size_t)2 * ROWS + row) * 64 + c];
    float4 r = make_float4((a.x + d.x + e.x) * inv, (a.y + d.y + e.y) * inv,
                           (a.z + d.z + e.z) * inv, (a.w + d.w + e.w) * inv);
    *(float4*)&out[(size_t)row * 64 + c] = r;
}

// ---------------------------------------------------------------------------
extern "C" void kernel_launch(void* const* d_in, const int* in_sizes, int n_in,
                              void* d_out, int out_size) {
    const float* x    = (const float*)d_in[0];
    const float* Wq   = (const float*)d_in[1];
    const float* Wk   = (const float*)d_in[2];
    const float* Wv   = (const float*)d_in[3];
    const int*   mask = (const int*)d_in[4];
    float*       out  = (float*)d_out;

    cudaFuncSetAttribute(proj_kernel, cudaFuncAttributeMaxDynamicSharedMemorySize,
                         PROJ_SMEM_B);
    cudaFuncSetAttribute(attn_kernel, cudaFuncAttributeMaxDynamicSharedMemorySize,
                         ATTN_SMEM_B);

    wcvt_kernel<<<192, 256>>>(Wq, Wk, Wv);
    proj_kernel<<<ROWS / 64, 256, PROJ_SMEM_B>>>(x);
    norm_kernel<<<ROWS / 128, 128>>>();
    attn_kernel<<<dim3(SEQ / 128, BATCH, KSPLIT), 128, ATTN_SMEM_B>>>(mask);
    combine_kernel<<<ROWS / 16, 256>>>(out);
}

// round 10
// speedup vs baseline: 1.3712x; 1.3569x over previous
#include <cuda_runtime.h>
#include <cuda_fp16.h>
#include <cstdint>

#define BATCH 4
#define SEQ   4096
#define EMBED 1024
#define HEAD  64
#define ROWS  (BATCH * SEQ)
#define KSPLIT 3

#define LOG2E 1.4426950408889634f

__device__ float  g_w [192 * EMBED];
__device__ __half g_q [ROWS * HEAD];        // fp16, h-window-permuted
__device__ __half g_k [ROWS * HEAD];        // fp16, h-window-permuted
__device__ __half g_vt[BATCH * HEAD * SEQ]; // fp16, key-window-permuted
__device__ float  g_qn[ROWS];
__device__ int    g_kmax_i[BATCH];
__device__ float  g_opart[KSPLIT * ROWS * HEAD];
__device__ float  g_l   [KSPLIT * ROWS];

// ---------------------------------------------------------------------------
__device__ __forceinline__ unsigned f2tf(float f) {
    unsigned u;
    asm("cvt.rna.tf32.f32 %0, %1;" : "=r"(u) : "f"(f));
    return u;
}
__device__ __forceinline__ float f2tff(float f) { return __uint_as_float(f2tf(f)); }

// tf32 m16n8k8 (projection)
__device__ __forceinline__ void mma8(float* d, unsigned a0, unsigned a1,
                                     unsigned a2, unsigned a3,
                                     unsigned b0, unsigned b1) {
    asm("mma.sync.aligned.m16n8k8.row.col.f32.tf32.tf32.f32 "
        "{%0,%1,%2,%3},{%4,%5,%6,%7},{%8,%9},{%0,%1,%2,%3};"
        : "+f"(d[0]), "+f"(d[1]), "+f"(d[2]), "+f"(d[3])
        : "r"(a0), "r"(a1), "r"(a2), "r"(a3), "r"(b0), "r"(b1));
}

// fp16 m16n8k16 (attention)
__device__ __forceinline__ void mma16(float* d, unsigned a0, unsigned a1,
                                      unsigned a2, unsigned a3,
                                      unsigned b0, unsigned b1) {
    asm("mma.sync.aligned.m16n8k16.row.col.f32.f16.f16.f32 "
        "{%0,%1,%2,%3},{%4,%5,%6,%7},{%8,%9},{%0,%1,%2,%3};"
        : "+f"(d[0]), "+f"(d[1]), "+f"(d[2]), "+f"(d[3])
        : "r"(a0), "r"(a1), "r"(a2), "r"(a3), "r"(b0), "r"(b1));
}

__device__ __forceinline__ unsigned packh2(float lo, float hi) {
    __half2 h = __floats2half2_rn(lo, hi);
    return *reinterpret_cast<unsigned*>(&h);
}

// window permutation: [l0,l1,l8,l9,l2,l3,l10,l11,l4,l5,l12,l13,l6,l7,l14,l15]
__device__ __forceinline__ int perm16(int idx) {
    int p = (idx & 15) >> 1;
    int slot = (p < 4) ? (2 * p) : (2 * p - 7);
    return (idx & ~15) + 2 * slot + (idx & 1);
}

__device__ __forceinline__ void cp16(void* sptr, const void* gaddr) {
    uint32_t sa = (uint32_t)__cvta_generic_to_shared(sptr);
    asm volatile("cp.async.ca.shared.global [%0], [%1], 16;" ::"r"(sa), "l"(gaddr));
}
__device__ __forceinline__ void cp_commit() { asm volatile("cp.async.commit_group;"); }

// ===========================================================================
// Weight pre-round + kmax init
// ===========================================================================
__global__ void __launch_bounds__(256) wcvt_kernel(const float* __restrict__ Wq,
                                                   const float* __restrict__ Wk,
                                                   const float* __restrict__ Wv) {
    if (blockIdx.x == 0 && threadIdx.x < BATCH) g_kmax_i[threadIdx.x] = 0;
    int idx4 = blockIdx.x * 256 + threadIdx.x;
    int n  = idx4 >> 8;
    int e4 = idx4 & 255;
    const float* src = (n < 64) ? Wq : (n < 128) ? Wk : Wv;
    float4 v = *(const float4*)(src + (size_t)(n & 63) * EMBED + 4 * e4);
    v.x = f2tff(v.x); v.y = f2tff(v.y); v.z = f2tff(v.z); v.w = f2tff(v.w);
    *(float4*)(g_w + (size_t)n * EMBED + 4 * e4) = v;
}

// ===========================================================================
// Projection (tf32 mma): tile 64 rows x 192 cols, 256 threads.
// Epilogue emits fp16 with window permutation (h for q/k, key for vt).
// ===========================================================================
#define PKC   32
#define PSTR  40
#define XS_F  (64 * PSTR)
#define WS_F  (192 * PSTR)
#define PROJ_SMEM_F (2 * (XS_F + WS_F))
#define PROJ_SMEM_B (PROJ_SMEM_F * 4)

__global__ void __launch_bounds__(256, 2)
proj_kernel(const float* __restrict__ x) {
    extern __shared__ float sm[];
    const int t = threadIdx.x, lane = t & 31, wid = t >> 5;
    const int g = lane >> 2, tq = lane & 3;
    const int wm = wid & 1, wn = wid >> 1;
    const size_t row0 = (size_t)blockIdx.x * 64;

    float acc[2][6][4];
#pragma unroll
    for (int mt = 0; mt < 2; mt++)
#pragma unroll
        for (int nt = 0; nt < 6; nt++)
#pragma unroll
            for (int i = 0; i < 4; i++) acc[mt][nt][i] = 0.f;

    const int NC = EMBED / PKC;

    auto issue = [&](int c) {
        int buf = c & 1;
        int k0  = c * PKC;
        float* Xs = sm + buf * (XS_F + WS_F);
        float* Ws = Xs + XS_F;
#pragma unroll
        for (int j = 0; j < 2; j++) {
            int id = t + 256 * j;
            int r = id >> 3, q = id & 7;
            cp16(&Xs[r * PSTR + 4 * q], x + (row0 + r) * EMBED + k0 + 4 * q);
        }
#pragma unroll
        for (int j = 0; j < 6; j++) {
            int id = t + 256 * j;
            int n = id >> 3, q = id & 7;
            cp16(&Ws[n * PSTR + 4 * q], g_w + (size_t)n * EMBED + k0 + 4 * q);
        }
        cp_commit();
    };

    issue(0);
    for (int c = 0; c < NC; c++) {
        if (c + 1 < NC) {
            issue(c + 1);
            asm volatile("cp.async.wait_group 1;");
        } else {
            asm volatile("cp.async.wait_group 0;");
        }
        __syncthreads();
        const float* Xs = sm + (c & 1) * (XS_F + WS_F);
        const float* Ws = Xs + XS_F;
#pragma unroll
        for (int kk = 0; kk < 4; kk++) {
            unsigned a[2][4];
#pragma unroll
            for (int mt = 0; mt < 2; mt++) {
                int r = 32 * wm + 16 * mt + g;
                float2 lo = *(const float2*)&Xs[(r    ) * PSTR + 8 * kk + 2 * tq];
                float2 hi = *(const float2*)&Xs[(r + 8) * PSTR + 8 * kk + 2 * tq];
                a[mt][0] = f2tf(lo.x); a[mt][1] = f2tf(hi.x);
                a[mt][2] = f2tf(lo.y); a[mt][3] = f2tf(hi.y);
            }
#pragma unroll
            for (int nt = 0; nt < 6; nt++) {
                uint2 bb = *(const uint2*)&Ws[(48 * wn + 8 * nt + g) * PSTR + 8 * kk + 2 * tq];
#pragma unroll
                for (int mt = 0; mt < 2; mt++)
                    mma8(acc[mt][nt], a[mt][0], a[mt][1], a[mt][2], a[mt][3],
                         bb.x, bb.y);
            }
        }
        __syncthreads();
    }

#pragma unroll
    for (int mt = 0; mt < 2; mt++) {
#pragma unroll
        for (int nt = 0; nt < 6; nt++) {
            int c0 = 48 * wn + 8 * nt + 2 * tq;
            int msel = c0 >> 6;
            int h    = c0 & 63;
            int r1 = (int)row0 + 32 * wm + 16 * mt + g;
            int r2 = r1 + 8;
            float* a = acc[mt][nt];
            if (msel == 0) {
                int hp = perm16(h);   // h even -> element 0 of its pair
                *(__half2*)&g_q[(size_t)r1 * 64 + hp] = __floats2half2_rn(a[0], a[1]);
                *(__half2*)&g_q[(size_t)r2 * 64 + hp] = __floats2half2_rn(a[2], a[3]);
            } else if (msel == 1) {
                int hp = perm16(h);
                *(__half2*)&g_k[(size_t)r1 * 64 + hp] = __floats2half2_rn(a[0], a[1]);
                *(__half2*)&g_k[(size_t)r2 * 64 + hp] = __floats2half2_rn(a[2], a[3]);
            } else {
                int b1 = r1 >> 12, n1 = r1 & 4095;
                int b2 = r2 >> 12, n2 = r2 & 4095;
                int np1 = perm16(n1), np2 = perm16(n2);
                g_vt[((size_t)b1 * 64 + h    ) * SEQ + np1] = __float2half_rn(a[0]);
                g_vt[((size_t)b1 * 64 + h + 1) * SEQ + np1] = __float2half_rn(a[1]);
                g_vt[((size_t)b2 * 64 + h    ) * SEQ + np2] = __float2half_rn(a[2]);
                g_vt[((size_t)b2 * 64 + h + 1) * SEQ + np2] = __float2half_rn(a[3]);
            }
        }
    }
}

// ===========================================================================
// Norms (over fp16 values actually used in the mma)
// ===========================================================================
__global__ void __launch_bounds__(128) norm_kernel() {
    int row = blockIdx.x * 128 + threadIdx.x;
    const __half2* qrow = (const __half2*)&g_q[(size_t)row * 64];
    const __half2* krow = (const __half2*)&g_k[(size_t)row * 64];
    float nq = 0.f, nk = 0.f;
#pragma unroll
    for (int i = 0; i < 32; i++) {
        float2 qf = __half22float2(qrow[i]);
        float2 kf = __half22float2(krow[i]);
        nq += qf.x * qf.x + qf.y * qf.y;
        nk += kf.x * kf.x + kf.y * kf.y;
    }
    g_qn[row] = sqrtf(nq);
    float nkr = sqrtf(nk);
#pragma unroll
    for (int d = 16; d; d >>= 1)
        nkr = fmaxf(nkr, __shfl_xor_sync(0xffffffffu, nkr, d));
    if ((threadIdx.x & 31) == 0)
        atomicMax(&g_kmax_i[row >> 12], __float_as_int(nkr));
}

// ===========================================================================
// Flash attention, fp16 m16n8k16, static max, fused S->exp->PV.
// Per 16-key window: 16 S-mmas (2 chunks x 2 rg x 4) -> exp -> pack P in
// registers (accumulator pairs == A-fragment) -> 16 PV-mmas.
// Smem: two 128x72-half regions (A doubles as Q staging); 37 KB, 3 CTAs/SM.
// ===========================================================================
#define STRH  72                        // halves per row (144 B, 16B-aligned)
#define REG_H (128 * STRH)              // 9216 halves per region
#define ATTN_SMEM_B (2 * REG_H * 2 + 512)  // 37376 B

__global__ void __launch_bounds__(128, 3)
attn_kernel(const int* __restrict__ mask) {
    extern __shared__ char smb[];
    __half* HA = (__half*)smb;                    // region A
    __half* HB = HA + REG_H;                      // region B
    float*  Mb = (float*)(smb + 2 * REG_H * 2);   // mask [2][64]

    const int t = threadIdx.x, lane = t & 31;
    const int g = lane >> 2, tq = lane & 3;
    const int r0 = (t >> 5) * 32;
    const int b  = blockIdx.y, z = blockIdx.z;
    const int q0 = blockIdx.x * 128;

    const int startTile = (z == 0) ? 0 : 22 + 21 * (z - 1);
    const int ntz       = (z == 0) ? 22 : 21;
    const int koff      = startTile * 64;

    const __half* qbase = g_q + ((size_t)b * SEQ + q0) * HEAD;
    const __half* kbase = g_k + ((size_t)b * SEQ + koff) * HEAD;
    const __half* vbase = g_vt + (size_t)b * HEAD * SEQ + koff;

    auto region = [&](int it) -> __half* { return (it & 1) ? HA : HB; };

    // ---- stage Q into region A (128 rows x 64 halves) ----
#pragma unroll
    for (int j = 0; j < 8; j++) {
        int id = t + 128 * j;               // 0..1023
        int r = id >> 3, q = id & 7;
        cp16(&HA[r * STRH + 8 * q], qbase + (size_t)r * 64 + 8 * q);
    }
    cp_commit();

    auto issue = [&](int it) {
        __half* Ks = region(it);
        __half* Vs = Ks + 64 * STRH;
#pragma unroll
        for (int j = 0; j < 8; j++) {
            int id = t + 128 * j;           // 0..1023
            int r = id >> 3, q = id & 7;
            if (r < 64)
                cp16(&Ks[r * STRH + 8 * q],
                     kbase + (size_t)(it * 64 + r) * 64 + 8 * q);
            else
                cp16(&Vs[(r - 64) * STRH + 8 * q],
                     vbase + (size_t)(r - 64) * SEQ + it * 64 + 8 * q);
        }
        if (t < 64)
            Mb[(it & 1) * 64 + t] =
                (mask[b * SEQ + koff + it * 64 + t] == 0) ? 0.f : 1.f;
        cp_commit();
    };

    issue(0);                               // tile 0 -> region B

    // ---- static row bounds (log2 domain) ----
    const float SC2 = 0.125f * LOG2E;
    const float kmax = __int_as_float(g_kmax_i[b]);
    float negM[2][2];
#pragma unroll
    for (int rg = 0; rg < 2; rg++) {
        size_t rr = (size_t)b * SEQ + q0 + r0 + 16 * rg + g;
        negM[rg][0] = -g_qn[rr]     * kmax * SC2;
        negM[rg][1] = -g_qn[rr + 8] * kmax * SC2;
    }

    asm volatile("cp.async.wait_group 1;"); // Q group drained
    __syncthreads();

    // ---- hoist Q fragments: [rg][k-window kk] = {a0,a1,a2,a3} ----
    unsigned qa[2][4][4];
#pragma unroll
    for (int rg = 0; rg < 2; rg++)
#pragma unroll
        for (int kk = 0; kk < 4; kk++) {
            int rlo = r0 + 16 * rg + g;
            uint2 ulo = *(const uint2*)&HA[rlo * STRH + 16 * kk + 4 * tq];
            uint2 uhi = *(const uint2*)&HA[(rlo + 8) * STRH + 16 * kk + 4 * tq];
            qa[rg][kk][0] = ulo.x;   // A[g][2tq,2tq+1]
            qa[rg][kk][1] = uhi.x;   // A[g+8][2tq,2tq+1]
            qa[rg][kk][2] = ulo.y;   // A[g][2tq+8,2tq+9]
            qa[rg][kk][3] = uhi.y;   // A[g+8][2tq+8,2tq+9]
        }
    __syncthreads();                        // done reading A
    if (1 < ntz) issue(1);                  // tile 1 -> region A

    float l[2][2] = {{0.f, 0.f}, {0.f, 0.f}};
    float o[2][8][4];
#pragma unroll
    for (int rg = 0; rg < 2; rg++)
#pragma unroll
        for (int nt = 0; nt < 8; nt++)
#pragma unroll
            for (int i = 0; i < 4; i++) o[rg][nt][i] = 0.f;

    for (int it = 0; it < ntz; it++) {
        if (it >= 1 && it + 1 < ntz) issue(it + 1);
        if (it + 1 < ntz) {
            asm volatile("cp.async.wait_group 1;");
        } else {
            asm volatile("cp.async.wait_group 0;");
        }
        __syncthreads();
        const __half* Ks = region(it);
        const __half* Vs = Ks + 64 * STRH;
        const float*  mk = Mb + (it & 1) * 64;

#pragma unroll
        for (int w = 0; w < 4; w++) {       // 16-key window
            // ---- S: two 8-col chunks (2w, 2w+1), both row groups ----
            float s[2][2][4];
#pragma unroll
            for (int c = 0; c < 2; c++)
#pragma unroll
                for (int rg = 0; rg < 2; rg++)
#pragma unroll
                    for (int i = 0; i < 4; i++) s[c][rg][i] = 0.f;
#pragma unroll
            for (int c = 0; c < 2; c++) {
                int nt = 2 * w + c;
#pragma unroll
                for (int kk = 0; kk < 4; kk++) {
                    uint2 bb = *(const uint2*)&Ks[(8 * nt + g) * STRH + 16 * kk + 4 * tq];
                    mma16(s[c][0], qa[0][kk][0], qa[0][kk][1], qa[0][kk][2],
                          qa[0][kk][3], bb.x, bb.y);
                    mma16(s[c][1], qa[1][kk][0], qa[1][kk][1], qa[1][kk][2],
                          qa[1][kk][3], bb.x, bb.y);
                }
            }
            // ---- static-max softmax + pack P fragments ----
            unsigned pa[2][4];              // [rg][a0..a3]
#pragma unroll
            for (int c = 0; c < 2; c++) {
                float2 mm = *(const float2*)&mk[8 * (2 * w + c) + 2 * tq];
#pragma unroll
                for (int rg = 0; rg < 2; rg++) {
                    float p0 = exp2f(fmaf(s[c][rg][0], SC2, negM[rg][0])) * mm.x;
                    float p1 = exp2f(fmaf(s[c][rg][1], SC2, negM[rg][0])) * mm.y;
                    float p2 = exp2f(fmaf(s[c][rg][2], SC2, negM[rg][1])) * mm.x;
                    float p3 = exp2f(fmaf(s[c][rg][3], SC2, negM[rg][1])) * mm.y;
                    l[rg][0] += p0 + p1;
                    l[rg][1] += p2 + p3;
                    pa[rg][2 * c    ] = packh2(p0, p1);  // row g   (a0 / a2)
                    pa[rg][2 * c + 1] = packh2(p2, p3);  // row g+8 (a1 / a3)
                }
            }
            // ---- PV: window w, all 64 head cols ----
#pragma unroll
            for (int nh = 0; nh < 8; nh++) {
                uint2 bb = *(const uint2*)&Vs[(8 * nh + g) * STRH + 16 * w + 4 * tq];
                mma16(o[0][nh], pa[0][0], pa[0][1], pa[0][2], pa[0][3], bb.x, bb.y);
                mma16(o[1][nh], pa[1][0], pa[1][1], pa[1][2], pa[1][3], bb.x, bb.y);
            }
        }
        __syncthreads();
    }

    // ---- epilogue: reduce l across tq, store unnormalized O + l ----
#pragma unroll
    for (int rg = 0; rg < 2; rg++)
#pragma unroll
        for (int h = 0; h < 2; h++) {
            l[rg][h] += __shfl_xor_sync(0xffffffffu, l[rg][h], 1);
            l[rg][h] += __shfl_xor_sync(0xffffffffu, l[rg][h], 2);
        }
#pragma unroll
    for (int rg = 0; rg < 2; rg++) {
        size_t rlo = (size_t)z * ROWS + (size_t)b * SEQ + q0 + r0 + 16 * rg + g;
        size_t rhi = rlo + 8;
#pragma unroll
        for (int nt = 0; nt < 8; nt++) {
            int c0 = 8 * nt + 2 * tq;
            *(float2*)&g_opart[rlo * 64 + c0] = make_float2(o[rg][nt][0], o[rg][nt][1]);
            *(float2*)&g_opart[rhi * 64 + c0] = make_float2(o[rg][nt][2], o[rg][nt][3]);
        }
        if (tq == 0) {
            g_l[rlo] = l[rg][0];
            g_l[rhi] = l[rg][1];
        }
    }
}

// ===========================================================================
// Split-K combine: shift M identical across splits -> plain sums.
// ===========================================================================
__global__ void __launch_bounds__(256) combine_kernel(float* __restrict__ out) {
    int t = threadIdx.x;
    int row = blockIdx.x * 16 + (t >> 4);
    int c   = (t & 15) * 4;
    float lsum = g_l[row] + g_l[ROWS + row] + g_l[2 * ROWS + row];
    float inv = 1.f / lsum;
    float4 a = *(const float4*)&g_opart[(size_t)row * 64 + c];
    float4 d = *(const float4*)&g_opart[((size_t)ROWS + row) * 64 + c];
    float4 e = *(const float4*)&g_opart[((size_t)2 * ROWS + row) * 64 + c];
    float4 r = make_float4((a.x + d.x + e.x) * inv, (a.y + d.y + e.y) * inv,
                           (a.z + d.z + e.z) * inv, (a.w + d.w + e.w) * inv);
    *(float4*)&out[(size_t)row * 64 + c] = r;
}

// ---------------------------------------------------------------------------
extern "C" void kernel_launch(void* const* d_in, const int* in_sizes, int n_in,
                              void* d_out, int out_size) {
    const float* x    = (const float*)d_in[0];
    const float* Wq   = (const float*)d_in[1];
    const float* Wk   = (const float*)d_in[2];
    const float* Wv   = (const float*)d_in[3];
    const int*   mask = (const int*)d_in[4];
    float*       out  = (float*)d_out;

    cudaFuncSetAttribute(proj_kernel, cudaFuncAttributeMaxDynamicSharedMemorySize,
                         PROJ_SMEM_B);
    cudaFuncSetAttribute(attn_kernel, cudaFuncAttributeMaxDynamicSharedMemorySize,
                         ATTN_SMEM_B);

    wcvt_kernel<<<192, 256>>>(Wq, Wk, Wv);
    proj_kernel<<<ROWS / 64, 256, PROJ_SMEM_B>>>(x);
    norm_kernel<<<ROWS / 128, 128>>>();
    attn_kernel<<<dim3(SEQ / 128, BATCH, KSPLIT), 128, ATTN_SMEM_B>>>(mask);
    combine_kernel<<<ROWS / 16, 256>>>(out);
}

// round 12
// speedup vs baseline: 1.5481x; 1.1290x over previous
#include <cuda_runtime.h>
#include <cuda_fp16.h>
#include <cstdint>

#define BATCH 4
#define SEQ   4096
#define EMBED 1024
#define HEAD  64
#define ROWS  (BATCH * SEQ)
#define KSPLIT 3

#define LOG2E 1.4426950408889634f

__device__ __half g_wh[192 * EMBED];        // fp16 W, e-window-permuted
__device__ __half g_q [ROWS * HEAD];        // fp16, h-window-permuted
__device__ __half g_k [ROWS * HEAD];        // fp16, h-window-permuted
__device__ __half g_vt[BATCH * HEAD * SEQ]; // fp16, key-window-permuted
__device__ float  g_qn[ROWS];
__device__ int    g_kmax_i[BATCH];
__device__ float  g_opart[KSPLIT * ROWS * HEAD];
__device__ float  g_l   [KSPLIT * ROWS];

// ---------------------------------------------------------------------------
// fp16 m16n8k16, f32 accumulate
__device__ __forceinline__ void mma16(float* d, unsigned a0, unsigned a1,
                                      unsigned a2, unsigned a3,
                                      unsigned b0, unsigned b1) {
    asm("mma.sync.aligned.m16n8k16.row.col.f32.f16.f16.f32 "
        "{%0,%1,%2,%3},{%4,%5,%6,%7},{%8,%9},{%0,%1,%2,%3};"
        : "+f"(d[0]), "+f"(d[1]), "+f"(d[2]), "+f"(d[3])
        : "r"(a0), "r"(a1), "r"(a2), "r"(a3), "r"(b0), "r"(b1));
}

__device__ __forceinline__ unsigned packh2(float lo, float hi) {
    __half2 h = __floats2half2_rn(lo, hi);
    return *reinterpret_cast<unsigned*>(&h);
}

// window permutation: pair p -> slot [0,2,4,6 | 1,3,5,7]
__device__ __forceinline__ int perm16(int idx) {
    int p = (idx & 15) >> 1;
    int slot = (p < 4) ? (2 * p) : (2 * p - 7);
    return (idx & ~15) + 2 * slot + (idx & 1);
}

__device__ __forceinline__ void cp16(void* sptr, const void* gaddr) {
    uint32_t sa = (uint32_t)__cvta_generic_to_shared(sptr);
    asm volatile("cp.async.ca.shared.global [%0], [%1], 16;" ::"r"(sa), "l"(gaddr));
}
__device__ __forceinline__ void cp_commit() { asm volatile("cp.async.commit_group;"); }

// ===========================================================================
// Weight convert: g_wh[n][e] = fp16(W[n][e]), e window-permuted. + kmax init
// ===========================================================================
__global__ void __launch_bounds__(256) wcvt_kernel(const float* __restrict__ Wq,
                                                   const float* __restrict__ Wk,
                                                   const float* __restrict__ Wv) {
    if (blockIdx.x == 0 && threadIdx.x < BATCH) g_kmax_i[threadIdx.x] = 0;
    int idx4 = blockIdx.x * 256 + threadIdx.x;
    int n  = idx4 >> 8;
    int e4 = idx4 & 255;
    int e  = 4 * e4;
    const float* src = (n < 64) ? Wq : (n < 128) ? Wk : Wv;
    float4 v = *(const float4*)(src + (size_t)(n & 63) * EMBED + e);
    *(__half2*)&g_wh[(size_t)n * EMBED + perm16(e)]     = __floats2half2_rn(v.x, v.y);
    *(__half2*)&g_wh[(size_t)n * EMBED + perm16(e + 2)] = __floats2half2_rn(v.z, v.w);
}

// ===========================================================================
// Projection (fp16 m16n8k16): tile 64 rows x 192 cols, 256 threads.
// X staged fp32 (A packed on the fly); W staged fp16 pre-permuted (raw B).
// Epilogue emits fp16 q/k/vt with window permutation.
// ===========================================================================
#define PKC   32
#define PSTR  40                        // floats per X row (chunk 32 + pad)
#define WSTR  40                        // halves per W row (chunk 32 + pad)
#define XS_B  (64 * PSTR * 4)           // 10240 B
#define WS_B  (192 * WSTR * 2)          // 15360 B
#define PROJ_BUF_B (XS_B + WS_B)        // 25600 B
#define PROJ_SMEM_B (2 * PROJ_BUF_B)    // 51200 B

__global__ void __launch_bounds__(256, 2)
proj_kernel(const float* __restrict__ x) {
    extern __shared__ char smc[];
    const int t = threadIdx.x, lane = t & 31, wid = t >> 5;
    const int g = lane >> 2, tq = lane & 3;
    const int wm = wid & 1, wn = wid >> 1;
    const size_t row0 = (size_t)blockIdx.x * 64;

    float acc[2][6][4];
#pragma unroll
    for (int mt = 0; mt < 2; mt++)
#pragma unroll
        for (int nt = 0; nt < 6; nt++)
#pragma unroll
            for (int i = 0; i < 4; i++) acc[mt][nt][i] = 0.f;

    const int NC = EMBED / PKC;

    auto issue = [&](int c) {
        char* buf = smc + (c & 1) * PROJ_BUF_B;
        float*  Xs = (float*)buf;
        __half* Ws = (__half*)(buf + XS_B);
        int k0 = c * PKC;
#pragma unroll
        for (int j = 0; j < 2; j++) {            // X: 64 rows x 32 f = 512 float4
            int id = t + 256 * j;
            int r = id >> 3, q = id & 7;
            cp16(&Xs[r * PSTR + 4 * q], x + (row0 + r) * EMBED + k0 + 4 * q);
        }
#pragma unroll
        for (int j = 0; j < 3; j++) {            // W: 192 rows x 32 h = 768 x 8h
            int id = t + 256 * j;                // 0..767
            int n = id >> 2, q = id & 3;         // 4 transfers of 8 halves per row
            cp16(&Ws[n * WSTR + 8 * q],
                 g_wh + (size_t)n * EMBED + k0 + 8 * q);
        }
        cp_commit();
    };

    issue(0);
    for (int c = 0; c < NC; c++) {
        if (c + 1 < NC) {
            issue(c + 1);
            asm volatile("cp.async.wait_group 1;");
        } else {
            asm volatile("cp.async.wait_group 0;");
        }
        __syncthreads();
        const char* buf = smc + (c & 1) * PROJ_BUF_B;
        const float*  Xs = (const float*)buf;
        const __half* Ws = (const __half*)(buf + XS_B);
#pragma unroll
        for (int kk = 0; kk < 2; kk++) {         // two k16 windows per chunk
            unsigned a[2][4];
#pragma unroll
            for (int mt = 0; mt < 2; mt++) {
                int r = 32 * wm + 16 * mt + g;
                float2 la = *(const float2*)&Xs[(r    ) * PSTR + 16 * kk + 2 * tq];
                float2 ha = *(const float2*)&Xs[(r + 8) * PSTR + 16 * kk + 2 * tq];
                float2 lb = *(const float2*)&Xs[(r    ) * PSTR + 16 * kk + 8 + 2 * tq];
                float2 hb = *(const float2*)&Xs[(r + 8) * PSTR + 16 * kk + 8 + 2 * tq];
                a[mt][0] = packh2(la.x, la.y);
                a[mt][1] = packh2(ha.x, ha.y);
                a[mt][2] = packh2(lb.x, lb.y);
                a[mt][3] = packh2(hb.x, hb.y);
            }
#pragma unroll
            for (int nt = 0; nt < 6; nt++) {
                uint2 bb = *(const uint2*)&Ws[(48 * wn + 8 * nt + g) * WSTR
                                              + 16 * kk + 4 * tq];
#pragma unroll
                for (int mt = 0; mt < 2; mt++)
                    mma16(acc[mt][nt], a[mt][0], a[mt][1], a[mt][2], a[mt][3],
                          bb.x, bb.y);
            }
        }
        __syncthreads();
    }

#pragma unroll
    for (int mt = 0; mt < 2; mt++) {
#pragma unroll
        for (int nt = 0; nt < 6; nt++) {
            int c0 = 48 * wn + 8 * nt + 2 * tq;
            int msel = c0 >> 6;
            int h    = c0 & 63;
            int r1 = (int)row0 + 32 * wm + 16 * mt + g;
            int r2 = r1 + 8;
            float* a = acc[mt][nt];
            if (msel == 0) {
                int hp = perm16(h);
                *(__half2*)&g_q[(size_t)r1 * 64 + hp] = __floats2half2_rn(a[0], a[1]);
                *(__half2*)&g_q[(size_t)r2 * 64 + hp] = __floats2half2_rn(a[2], a[3]);
            } else if (msel == 1) {
                int hp = perm16(h);
                *(__half2*)&g_k[(size_t)r1 * 64 + hp] = __floats2half2_rn(a[0], a[1]);
                *(__half2*)&g_k[(size_t)r2 * 64 + hp] = __floats2half2_rn(a[2], a[3]);
            } else {
                int b1 = r1 >> 12, n1 = r1 & 4095;
                int b2 = r2 >> 12, n2 = r2 & 4095;
                int np1 = perm16(n1), np2 = perm16(n2);
                g_vt[((size_t)b1 * 64 + h    ) * SEQ + np1] = __float2half_rn(a[0]);
                g_vt[((size_t)b1 * 64 + h + 1) * SEQ + np1] = __float2half_rn(a[1]);
                g_vt[((size_t)b2 * 64 + h    ) * SEQ + np2] = __float2half_rn(a[2]);
                g_vt[((size_t)b2 * 64 + h + 1) * SEQ + np2] = __float2half_rn(a[3]);
            }
        }
    }
}

// ===========================================================================
// Norms (over the fp16 values actually fed to the mma; perm-invariant)
// ===========================================================================
__global__ void __launch_bounds__(128) norm_kernel() {
    int row = blockIdx.x * 128 + threadIdx.x;
    const __half2* qrow = (const __half2*)&g_q[(size_t)row * 64];
    const __half2* krow = (const __half2*)&g_k[(size_t)row * 64];
    float nq = 0.f, nk = 0.f;
#pragma unroll
    for (int i = 0; i < 32; i++) {
        float2 qf = __half22float2(qrow[i]);
        float2 kf = __half22float2(krow[i]);
        nq += qf.x * qf.x + qf.y * qf.y;
        nk += kf.x * kf.x + kf.y * kf.y;
    }
    g_qn[row] = sqrtf(nq);
    float nkr = sqrtf(nk);
#pragma unroll
    for (int d = 16; d; d >>= 1)
        nkr = fmaxf(nkr, __shfl_xor_sync(0xffffffffu, nkr, d));
    if ((threadIdx.x & 31) == 0)
        atomicMax(&g_kmax_i[row >> 12], __float_as_int(nkr));
}

// ===========================================================================
// Flash attention, fp16 m16n8k16, static max, fused S->exp->PV. (unchanged)
// ===========================================================================
#define STRH  72
#define REG_H (128 * STRH)
#define ATTN_SMEM_B (2 * REG_H * 2 + 512)

__global__ void __launch_bounds__(128, 3)
attn_kernel(const int* __restrict__ mask) {
    extern __shared__ char smb[];
    __half* HA = (__half*)smb;
    __half* HB = HA + REG_H;
    float*  Mb = (float*)(smb + 2 * REG_H * 2);

    const int t = threadIdx.x, lane = t & 31;
    const int g = lane >> 2, tq = lane & 3;
    const int r0 = (t >> 5) * 32;
    const int b  = blockIdx.y, z = blockIdx.z;
    const int q0 = blockIdx.x * 128;

    const int startTile = (z == 0) ? 0 : 22 + 21 * (z - 1);
    const int ntz       = (z == 0) ? 22 : 21;
    const int koff      = startTile * 64;

    const __half* qbase = g_q + ((size_t)b * SEQ + q0) * HEAD;
    const __half* kbase = g_k + ((size_t)b * SEQ + koff) * HEAD;
    const __half* vbase = g_vt + (size_t)b * HEAD * SEQ + koff;

    auto region = [&](int it) -> __half* { return (it & 1) ? HA : HB; };

#pragma unroll
    for (int j = 0; j < 8; j++) {
        int id = t + 128 * j;
        int r = id >> 3, q = id & 7;
        cp16(&HA[r * STRH + 8 * q], qbase + (size_t)r * 64 + 8 * q);
    }
    cp_commit();

    auto issue = [&](int it) {
        __half* Ks = region(it);
        __half* Vs = Ks + 64 * STRH;
#pragma unroll
        for (int j = 0; j < 8; j++) {
            int id = t + 128 * j;
            int r = id >> 3, q = id & 7;
            if (r < 64)
                cp16(&Ks[r * STRH + 8 * q],
                     kbase + (size_t)(it * 64 + r) * 64 + 8 * q);
            else
                cp16(&Vs[(r - 64) * STRH + 8 * q],
                     vbase + (size_t)(r - 64) * SEQ + it * 64 + 8 * q);
        }
        if (t < 64)
            Mb[(it & 1) * 64 + t] =
                (mask[b * SEQ + koff + it * 64 + t] == 0) ? 0.f : 1.f;
        cp_commit();
    };

    issue(0);

    const float SC2 = 0.125f * LOG2E;
    const float kmax = __int_as_float(g_kmax_i[b]);
    float negM[2][2];
#pragma unroll
    for (int rg = 0; rg < 2; rg++) {
        size_t rr = (size_t)b * SEQ + q0 + r0 + 16 * rg + g;
        negM[rg][0] = -g_qn[rr]     * kmax * SC2;
        negM[rg][1] = -g_qn[rr + 8] * kmax * SC2;
    }

    asm volatile("cp.async.wait_group 1;");
    __syncthreads();

    unsigned qa[2][4][4];
#pragma unroll
    for (int rg = 0; rg < 2; rg++)
#pragma unroll
        for (int kk = 0; kk < 4; kk++) {
            int rlo = r0 + 16 * rg + g;
            uint2 ulo = *(const uint2*)&HA[rlo * STRH + 16 * kk + 4 * tq];
            uint2 uhi = *(const uint2*)&HA[(rlo + 8) * STRH + 16 * kk + 4 * tq];
            qa[rg][kk][0] = ulo.x;
            qa[rg][kk][1] = uhi.x;
            qa[rg][kk][2] = ulo.y;
            qa[rg][kk][3] = uhi.y;
        }
    __syncthreads();
    if (1 < ntz) issue(1);

    float l[2][2] = {{0.f, 0.f}, {0.f, 0.f}};
    float o[2][8][4];
#pragma unroll
    for (int rg = 0; rg < 2; rg++)
#pragma unroll
        for (int nt = 0; nt < 8; nt++)
#pragma unroll
            for (int i = 0; i < 4; i++) o[rg][nt][i] = 0.f;

    for (int it = 0; it < ntz; it++) {
        if (it >= 1 && it + 1 < ntz) issue(it + 1);
        if (it + 1 < ntz) {
            asm volatile("cp.async.wait_group 1;");
        } else {
            asm volatile("cp.async.wait_group 0;");
        }
        __syncthreads();
        const __half* Ks = region(it);
        const __half* Vs = Ks + 64 * STRH;
        const float*  mk = Mb + (it & 1) * 64;

#pragma unroll
        for (int w = 0; w < 4; w++) {
            float s[2][2][4];
#pragma unroll
            for (int c = 0; c < 2; c++)
#pragma unroll
                for (int rg = 0; rg < 2; rg++)
#pragma unroll
                    for (int i = 0; i < 4; i++) s[c][rg][i] = 0.f;
#pragma unroll
            for (int c = 0; c < 2; c++) {
                int nt = 2 * w + c;
#pragma unroll
                for (int kk = 0; kk < 4; kk++) {
                    uint2 bb = *(const uint2*)&Ks[(8 * nt + g) * STRH + 16 * kk + 4 * tq];
                    mma16(s[c][0], qa[0][kk][0], qa[0][kk][1], qa[0][kk][2],
                          qa[0][kk][3], bb.x, bb.y);
                    mma16(s[c][1], qa[1][kk][0], qa[1][kk][1], qa[1][kk][2],
                          qa[1][kk][3], bb.x, bb.y);
                }
            }
            unsigned pa[2][4];
#pragma unroll
            for (int c = 0; c < 2; c++) {
                float2 mm = *(const float2*)&mk[8 * (2 * w + c) + 2 * tq];
#pragma unroll
                for (int rg = 0; rg < 2; rg++) {
                    float p0 = exp2f(fmaf(s[c][rg][0], SC2, negM[rg][0])) * mm.x;
                    float p1 = exp2f(fmaf(s[c][rg][1], SC2, negM[rg][0])) * mm.y;
                    float p2 = exp2f(fmaf(s[c][rg][2], SC2, negM[rg][1])) * mm.x;
                    float p3 = exp2f(fmaf(s[c][rg][3], SC2, negM[rg][1])) * mm.y;
                    l[rg][0] += p0 + p1;
                    l[rg][1] += p2 + p3;
                    pa[rg][2 * c    ] = packh2(p0, p1);
                    pa[rg][2 * c + 1] = packh2(p2, p3);
                }
            }
#pragma unroll
            for (int nh = 0; nh < 8; nh++) {
                uint2 bb = *(const uint2*)&Vs[(8 * nh + g) * STRH + 16 * w + 4 * tq];
                mma16(o[0][nh], pa[0][0], pa[0][1], pa[0][2], pa[0][3], bb.x, bb.y);
                mma16(o[1][nh], pa[1][0], pa[1][1], pa[1][2], pa[1][3], bb.x, bb.y);
            }
        }
        __syncthreads();
    }

#pragma unroll
    for (int rg = 0; rg < 2; rg++)
#pragma unroll
        for (int h = 0; h < 2; h++) {
            l[rg][h] += __shfl_xor_sync(0xffffffffu, l[rg][h], 1);
            l[rg][h] += __shfl_xor_sync(0xffffffffu, l[rg][h], 2);
        }
#pragma unroll
    for (int rg = 0; rg < 2; rg++) {
        size_t rlo = (size_t)z * ROWS + (size_t)b * SEQ + q0 + r0 + 16 * rg + g;
        size_t rhi = rlo + 8;
#pragma unroll
        for (int nt = 0; nt < 8; nt++) {
            int c0 = 8 * nt + 2 * tq;
            *(float2*)&g_opart[rlo * 64 + c0] = make_float2(o[rg][nt][0], o[rg][nt][1]);
            *(float2*)&g_opart[rhi * 64 + c0] = make_float2(o[rg][nt][2], o[rg][nt][3]);
        }
        if (tq == 0) {
            g_l[rlo] = l[rg][0];
            g_l[rhi] = l[rg][1];
        }
    }
}

// ===========================================================================
// Split-K combine
// ===========================================================================
__global__ void __launch_bounds__(256) combine_kernel(float* __restrict__ out) {
    int t = threadIdx.x;
    int row = blockIdx.x * 16 + (t >> 4);
    int c   = (t & 15) * 4;
    float lsum = g_l[row] + g_l[ROWS + row] + g_l[2 * ROWS + row];
    float inv = 1.f / lsum;
    float4 a = *(const float4*)&g_opart[(size_t)row * 64 + c];
    float4 d = *(const float4*)&g_opart[((size_t)ROWS + row) * 64 + c];
    float4 e = *(const float4*)&g_opart[((size_t)2 * ROWS + row) * 64 + c];
    float4 r = make_float4((a.x + d.x + e.x) * inv, (a.y + d.y + e.y) * inv,
                           (a.z + d.z + e.z) * inv, (a.w + d.w + e.w) * inv);
    *(float4*)&out[(size_t)row * 64 + c] = r;
}

// ---------------------------------------------------------------------------
extern "C" void kernel_launch(void* const* d_in, const int* in_sizes, int n_in,
                              void* d_out, int out_size) {
    const float* x    = (const float*)d_in[0];
    const float* Wq   = (const float*)d_in[1];
    const float* Wk   = (const float*)d_in[2];
    const float* Wv   = (const float*)d_in[3];
    const int*   mask = (const int*)d_in[4];
    float*       out  = (float*)d_out;

    cudaFuncSetAttribute(proj_kernel, cudaFuncAttributeMaxDynamicSharedMemorySize,
                         PROJ_SMEM_B);
    cudaFuncSetAttribute(attn_kernel, cudaFuncAttributeMaxDynamicSharedMemorySize,
                         ATTN_SMEM_B);

    wcvt_kernel<<<192, 256>>>(Wq, Wk, Wv);
    proj_kernel<<<ROWS / 64, 256, PROJ_SMEM_B>>>(x);
    norm_kernel<<<ROWS / 128, 128>>>();
    attn_kernel<<<dim3(SEQ / 128, BATCH, KSPLIT), 128, ATTN_SMEM_B>>>(mask);
    combine_kernel<<<ROWS / 16, 256>>>(out);
}